// round 11
// baseline (speedup 1.0000x reference)
#include <cuda_runtime.h>
#include <cuda_bf16.h>
#include <math.h>
#include <mma.h>

using namespace nvcuda;

#define IN_CH 128
#define H 4
#define C 16
#define HC 64
#define MAXN 100000
#define MAXE 1600000
#define NEG_SLOPE 0.2f
#define SCAN_BLK 512
#define FDEG 32          // cached slots per node in fuse

// gemm smem layout (floats)
#define SXLD 136
#define SWLD 72
#define OFF_XH 0
#define OFF_XL (64 * SXLD)
#define OFF_WH (2 * 64 * SXLD)
#define OFF_WL (2 * 64 * SXLD + IN_CH * SWLD)
#define GEMM_SMEM_FLOATS (2 * 64 * SXLD + 2 * IN_CH * SWLD)
#define GEMM_SMEM_BYTES (GEMM_SMEM_FLOATS * 4)

// scratch (device globals — allocation is forbidden)
__device__ __align__(16) float g_xp[MAXN * HC];      // 25.6 MB
__device__ __align__(16) float g_asrc[MAXN * H];
__device__ __align__(16) float g_adst[MAXN * H];
__device__ int  g_cnt[MAXN];        // zero-initialized; self-restored each call
__device__ int  g_rowptr[MAXN];     // partial (within-block) exclusive prefix
__device__ int  g_woff[MAXN];       // copy of partial prefix, atomically bumped
__device__ int  g_bsum[SCAN_BLK];
__device__ int  g_boff[SCAN_BLK];
__device__ int  g_scancnt;          // block-done counter; self-restored
__device__ int2 g_sedge[MAXE];      // (src, orig edge id), dst-sorted

__device__ __forceinline__ float4 leaky_exp4(float4 as, float4 ad) {
    float4 l;
    l.x = as.x + ad.x; l.x = l.x > 0.f ? l.x : NEG_SLOPE * l.x;
    l.y = as.y + ad.y; l.y = l.y > 0.f ? l.y : NEG_SLOPE * l.y;
    l.z = as.z + ad.z; l.z = l.z > 0.f ? l.z : NEG_SLOPE * l.z;
    l.w = as.w + ad.w; l.w = l.w > 0.f ? l.w : NEG_SLOPE * l.w;
    float4 ev;
    ev.x = __expf(l.x); ev.y = __expf(l.y);
    ev.z = __expf(l.z); ev.w = __expf(l.w);
    return ev;
}

// ---------------------------------------------------------------------------
// K-hist: histogram of dst (int4, 4 atomics/thread). dst half only.
// ---------------------------------------------------------------------------
__global__ void k_hist4(const int* __restrict__ ei, int e) {
    const int4* d4p = (const int4*)(ei + e);
    int q = e >> 2;
    for (int i = blockIdx.x * blockDim.x + threadIdx.x; i < q;
         i += gridDim.x * blockDim.x) {
        int4 d = d4p[i];
        atomicAdd(&g_cnt[d.x], 1);
        atomicAdd(&g_cnt[d.y], 1);
        atomicAdd(&g_cnt[d.z], 1);
        atomicAdd(&g_cnt[d.w], 1);
    }
}
__global__ void k_hist1(const int* __restrict__ ei, int e) {   // fallback
    for (int i = blockIdx.x * blockDim.x + threadIdx.x; i < e;
         i += gridDim.x * blockDim.x)
        atomicAdd(&g_cnt[ei[e + i]], 1);
}

// ---------------------------------------------------------------------------
// K-scan: per-block exclusive scan of g_cnt (self-zeroing) -> rowptr/woff
// (partial); last finished block scans the block sums -> g_boff.
// ---------------------------------------------------------------------------
__global__ __launch_bounds__(SCAN_BLK) void k_scan(int n) {
    __shared__ int s[SCAN_BLK];
    __shared__ int lastdone;
    int t = threadIdx.x;
    int i = blockIdx.x * SCAN_BLK + t;
    int v = 0;
    if (i < n) {
        v = g_cnt[i];
        g_cnt[i] = 0;
    }
    s[t] = v;
    __syncthreads();
    #pragma unroll
    for (int off = 1; off < SCAN_BLK; off <<= 1) {
        int a = (t >= off) ? s[t - off] : 0;
        __syncthreads();
        s[t] += a;
        __syncthreads();
    }
    if (i < n) {
        int r = s[t] - v;
        g_rowptr[i] = r;
        g_woff[i] = r;
    }
    if (t == SCAN_BLK - 1) g_bsum[blockIdx.x] = s[t];

    __threadfence();
    if (t == 0) {
        int d = atomicAdd(&g_scancnt, 1);
        lastdone = (d == gridDim.x - 1);
    }
    __syncthreads();
    if (!lastdone) return;
    int nb = gridDim.x;
    int bv = (t < nb) ? g_bsum[t] : 0;
    s[t] = bv;
    __syncthreads();
    #pragma unroll
    for (int off = 1; off < SCAN_BLK; off <<= 1) {
        int a = (t >= off) ? s[t - off] : 0;
        __syncthreads();
        s[t] += a;
        __syncthreads();
    }
    g_boff[t] = s[t] - bv;
    if (t == 0) g_scancnt = 0;
}

// ---------------------------------------------------------------------------
// K-permute: 4 edges/thread (int4 loads), scatter into dst-sorted order,
// and produce the edge_index float copy.
// ---------------------------------------------------------------------------
__global__ void k_permute4(const int* __restrict__ ei,
                           float* __restrict__ out_ei, int e) {
    int q = e >> 2;
    int i = blockIdx.x * blockDim.x + threadIdx.x;
    if (i >= q) return;
    int4 s4 = ((const int4*)ei)[i];
    int4 d4 = ((const int4*)(ei + e))[i];
    if (out_ei) {
        float4 fs = make_float4((float)s4.x, (float)s4.y,
                                (float)s4.z, (float)s4.w);
        float4 fd = make_float4((float)d4.x, (float)d4.y,
                                (float)d4.z, (float)d4.w);
        ((float4*)out_ei)[i] = fs;
        ((float4*)(out_ei + e))[i] = fd;
    }
    int base = i * 4;
    int r0 = atomicAdd(&g_woff[d4.x], 1) + g_boff[d4.x >> 9];
    int r1 = atomicAdd(&g_woff[d4.y], 1) + g_boff[d4.y >> 9];
    int r2 = atomicAdd(&g_woff[d4.z], 1) + g_boff[d4.z >> 9];
    int r3 = atomicAdd(&g_woff[d4.w], 1) + g_boff[d4.w >> 9];
    g_sedge[r0] = make_int2(s4.x, base);
    g_sedge[r1] = make_int2(s4.y, base + 1);
    g_sedge[r2] = make_int2(s4.z, base + 2);
    g_sedge[r3] = make_int2(s4.w, base + 3);
}
__global__ void k_permute1(const int* __restrict__ ei,
                           float* __restrict__ out_ei, int e) {  // fallback
    int i = blockIdx.x * blockDim.x + threadIdx.x;
    if (i >= e) return;
    int src = ei[i], dst = ei[e + i];
    if (out_ei) { out_ei[i] = (float)src; out_ei[e + i] = (float)dst; }
    int r = atomicAdd(&g_woff[dst], 1) + g_boff[dst >> 9];
    g_sedge[r] = make_int2(src, i);
}

// ---------------------------------------------------------------------------
// K-gemm_tc: xp = x @ W via 3xTF32 wmma (m16n16k8). 64 nodes/block.
// 8 warps: warp w -> row-tile (w>>1), col-tiles {2*(w&1), 2*(w&1)+1}.
// Epilogue: C staged in smem; 4 threads/node compute a_src/a_dst + write xp.
// ---------------------------------------------------------------------------
__global__ __launch_bounds__(256) void k_gemm_tc(
        const float* __restrict__ x, const float* __restrict__ W,
        const float* __restrict__ att_src, const float* __restrict__ att_dst,
        int n) {
    extern __shared__ float sm[];
    float* sxh = sm + OFF_XH;
    float* sxl = sm + OFF_XL;
    float* sWh = sm + OFF_WH;
    float* sWl = sm + OFF_WL;
    float* sC  = sm;                 // alias over sxh after mainloop

    int tid = threadIdx.x;
    int node0 = blockIdx.x * 64;

    // load W -> hi/lo tf32 split
    for (int idx = tid; idx < IN_CH * HC; idx += 256) {
        int r = idx >> 6, c = idx & 63;
        float v = W[idx];
        float hi = wmma::__float_to_tf32(v);
        sWh[r * SWLD + c] = hi;
        sWl[r * SWLD + c] = wmma::__float_to_tf32(v - hi);
    }
    // load x tile -> hi/lo
    for (int idx = tid; idx < 64 * IN_CH; idx += 256) {
        int nn = idx >> 7, k = idx & 127;
        int node = node0 + nn;
        float v = (node < n) ? x[(size_t)node * IN_CH + k] : 0.f;
        float hi = wmma::__float_to_tf32(v);
        sxh[nn * SXLD + k] = hi;
        sxl[nn * SXLD + k] = wmma::__float_to_tf32(v - hi);
    }
    __syncthreads();

    int w = tid >> 5;
    int rt = w >> 1;                 // row tile 0..3
    int ct0 = (w & 1) * 2;           // first col tile (0 or 2)

    wmma::fragment<wmma::matrix_a, 16, 16, 8, wmma::precision::tf32,
                   wmma::row_major> ah, al;
    wmma::fragment<wmma::matrix_b, 16, 16, 8, wmma::precision::tf32,
                   wmma::row_major> bh, bl;
    wmma::fragment<wmma::accumulator, 16, 16, 8, float> c0, c1;
    wmma::fill_fragment(c0, 0.f);
    wmma::fill_fragment(c1, 0.f);

    #pragma unroll
    for (int k = 0; k < IN_CH / 8; k++) {
        wmma::load_matrix_sync(ah, &sxh[rt * 16 * SXLD + k * 8], SXLD);
        wmma::load_matrix_sync(al, &sxl[rt * 16 * SXLD + k * 8], SXLD);
        wmma::load_matrix_sync(bh, &sWh[k * 8 * SWLD + ct0 * 16], SWLD);
        wmma::load_matrix_sync(bl, &sWl[k * 8 * SWLD + ct0 * 16], SWLD);
        wmma::mma_sync(c0, ah, bh, c0);
        wmma::mma_sync(c0, ah, bl, c0);
        wmma::mma_sync(c0, al, bh, c0);
        wmma::load_matrix_sync(bh, &sWh[k * 8 * SWLD + (ct0 + 1) * 16], SWLD);
        wmma::load_matrix_sync(bl, &sWl[k * 8 * SWLD + (ct0 + 1) * 16], SWLD);
        wmma::mma_sync(c1, ah, bh, c1);
        wmma::mma_sync(c1, ah, bl, c1);
        wmma::mma_sync(c1, al, bh, c1);
    }
    __syncthreads();   // done reading sxh/sxl; safe to alias sC
    wmma::store_matrix_sync(&sC[rt * 16 * SWLD + ct0 * 16], c0, SWLD,
                            wmma::mem_row_major);
    wmma::store_matrix_sync(&sC[rt * 16 * SWLD + (ct0 + 1) * 16], c1, SWLD,
                            wmma::mem_row_major);
    __syncthreads();

    // epilogue: 4 threads/node; thread handles head q (16 cols)
    int nl = tid >> 2;       // local node 0..63
    int q  = tid & 3;        // head
    int node = node0 + nl;
    if (node < n) {
        const float* row = &sC[nl * SWLD + q * 16];
        float s = 0.f, d = 0.f;
        #pragma unroll
        for (int i = 0; i < 4; i++) {
            float4 v = *(const float4*)&row[i * 4];
            const float4 a_s = ((const float4*)att_src)[q * 4 + i];
            const float4 a_d = ((const float4*)att_dst)[q * 4 + i];
            s += v.x * a_s.x + v.y * a_s.y + v.z * a_s.z + v.w * a_s.w;
            d += v.x * a_d.x + v.y * a_d.y + v.z * a_d.z + v.w * a_d.w;
            ((float4*)g_xp)[(size_t)node * 16 + q * 4 + i] = v;
        }
        g_asrc[node * H + q] = s;
        g_adst[node * H + q] = d;
    }
}

// ---------------------------------------------------------------------------
// K-fuse: HALF-WARP (16 lanes) per dst node. Lane owns float4 (4 cols).
// ---------------------------------------------------------------------------
__global__ __launch_bounds__(256) void k_fuse(
        const float* __restrict__ bias, float* __restrict__ out,
        float* __restrict__ out_alpha, int n, int e) {
    __shared__ float4 s_ev[16][FDEG];   // 8 KB
    __shared__ int2   s_se[16][FDEG];   // 4 KB
    int g = threadIdx.x >> 4;
    int l = threadIdx.x & 15;
    unsigned gmask = 0xFFFFu << ((g & 1) * 16);
    int node = blockIdx.x * 16 + g;
    if (node >= n) return;
    int start = g_rowptr[node] + g_boff[node >> 9];
    int end = (node == n - 1) ? e
            : g_rowptr[node + 1] + g_boff[(node + 1) >> 9];
    int deg = end - start;
    float4 ad = ((const float4*)g_adst)[node];

    float4 sum = make_float4(0.f, 0.f, 0.f, 0.f);
    for (int slot = l; slot < deg; slot += 16) {
        int2 se = g_sedge[start + slot];
        float4 as = ((const float4*)g_asrc)[se.x];
        float4 ev = leaky_exp4(as, ad);
        if (slot < FDEG) {
            s_ev[g][slot] = ev;
            s_se[g][slot] = se;
        }
        sum.x += ev.x; sum.y += ev.y; sum.z += ev.z; sum.w += ev.w;
    }
    #pragma unroll
    for (int off = 8; off >= 1; off >>= 1) {
        sum.x += __shfl_xor_sync(gmask, sum.x, off);
        sum.y += __shfl_xor_sync(gmask, sum.y, off);
        sum.z += __shfl_xor_sync(gmask, sum.z, off);
        sum.w += __shfl_xor_sync(gmask, sum.w, off);
    }
    float4 inv;
    inv.x = 1.f / (sum.x + 1e-16f);
    inv.y = 1.f / (sum.y + 1e-16f);
    inv.z = 1.f / (sum.z + 1e-16f);
    inv.w = 1.f / (sum.w + 1e-16f);
    __syncwarp(gmask);

    int h = l >> 2;
    float invh = (h == 0) ? inv.x : (h == 1) ? inv.y :
                 (h == 2) ? inv.z : inv.w;
    float4 acc = make_float4(0.f, 0.f, 0.f, 0.f);

    for (int base = 0; base < deg; base += 16) {
        int m = deg - base; if (m > 16) m = 16;
        int slot = base + l;
        if (slot >= FDEG && l < m) {
            int2 se = g_sedge[start + slot];
            float4 as = ((const float4*)g_asrc)[se.x];
            s_ev[g][slot & (FDEG - 1)] = leaky_exp4(as, ad);
            s_se[g][slot & (FDEG - 1)] = se;
        }
        __syncwarp(gmask);
        if (l < m && out_alpha) {
            int idx = slot & (FDEG - 1);
            float4 ev = s_ev[g][idx];
            float4 al;
            al.x = ev.x * inv.x; al.y = ev.y * inv.y;
            al.z = ev.z * inv.z; al.w = ev.w * inv.w;
            ((float4*)out_alpha)[s_se[g][idx].y] = al;
        }
        #pragma unroll 4
        for (int j = 0; j < m; j++) {
            int idx = (base + j) & (FDEG - 1);
            int src = s_se[g][idx].x;
            float a = ((const float*)&s_ev[g][idx])[h] * invh;
            float4 v = ((const float4*)&g_xp[(size_t)src * HC])[l];
            acc.x = fmaf(v.x, a, acc.x);
            acc.y = fmaf(v.y, a, acc.y);
            acc.z = fmaf(v.z, a, acc.z);
            acc.w = fmaf(v.w, a, acc.w);
        }
        __syncwarp(gmask);
    }
    float4 b = ((const float4*)bias)[l];
    float4 o;
    o.x = acc.x + b.x; o.y = acc.y + b.y;
    o.z = acc.z + b.z; o.w = acc.w + b.w;
    ((float4*)&out[(size_t)node * HC])[l] = o;
}

// lazily-created side stream + events (resource init only; the launched work
// is identical on every call, so graph capture sees the same graph each time)
static cudaStream_t g_s2 = nullptr;
static cudaEvent_t  g_evFork = nullptr, g_evJoin = nullptr;
static bool g_attrSet = false;

extern "C" void kernel_launch(void* const* d_in, const int* in_sizes, int n_in,
                              void* d_out, int out_size) {
    const float* x       = (const float*)d_in[0];
    const float* W       = (const float*)d_in[1];
    const float* att_src = (const float*)d_in[2];
    const float* att_dst = (const float*)d_in[3];
    const float* bias    = (const float*)d_in[4];
    const int*   ei      = (const int*)d_in[5];

    if (!g_s2) {
        cudaStreamCreateWithFlags(&g_s2, cudaStreamNonBlocking);
        cudaEventCreateWithFlags(&g_evFork, cudaEventDisableTiming);
        cudaEventCreateWithFlags(&g_evJoin, cudaEventDisableTiming);
    }
    if (!g_attrSet) {
        cudaFuncSetAttribute(k_gemm_tc,
                             cudaFuncAttributeMaxDynamicSharedMemorySize,
                             GEMM_SMEM_BYTES);
        g_attrSet = true;
    }

    int n = in_sizes[0] / IN_CH;
    int e = in_sizes[5] / 2;

    float* out = (float*)d_out;
    float* out_ei = nullptr;
    float* out_alpha = nullptr;
    if (out_size >= n * HC + 2 * e) out_ei = out + (size_t)n * HC;
    if (out_size >= n * HC + 2 * e + e * H)
        out_alpha = out + (size_t)n * HC + 2 * e;

    // ---- fork: GEMM on side stream (independent of CSR build) ----
    cudaEventRecord(g_evFork, 0);
    cudaStreamWaitEvent(g_s2, g_evFork, 0);
    k_gemm_tc<<<(n + 63) / 64, 256, GEMM_SMEM_BYTES, g_s2>>>(
        x, W, att_src, att_dst, n);
    cudaEventRecord(g_evJoin, g_s2);

    // ---- main stream: CSR build ----
    bool vec = ((e & 3) == 0);
    if (vec) {
        int q = e >> 2;
        int blocks = (q + 255) / 256;
        if (blocks > 2048) blocks = 2048;
        k_hist4<<<blocks, 256>>>(ei, e);
    } else {
        int blocks = (e + 255) / 256;
        if (blocks > 4096) blocks = 4096;
        k_hist1<<<blocks, 256>>>(ei, e);
    }
    int nb = (n + SCAN_BLK - 1) / SCAN_BLK;
    k_scan<<<nb, SCAN_BLK>>>(n);
    if (vec) {
        int q = e >> 2;
        k_permute4<<<(q + 255) / 256, 256>>>(ei, out_ei, e);
    } else {
        k_permute1<<<(e + 255) / 256, 256>>>(ei, out_ei, e);
    }

    // ---- join: fuse needs both GEMM results and sorted edges ----
    cudaStreamWaitEvent(0, g_evJoin, 0);
    k_fuse<<<(n + 15) / 16, 256>>>(bias, out, out_alpha, n, e);
}

// round 14
// speedup vs baseline: 1.5800x; 1.5800x over previous
#include <cuda_runtime.h>
#include <cuda_fp16.h>
#include <math.h>

#define IN_CH 128
#define H 4
#define C 16
#define HC 64
#define MAXN 100000
#define MAXE 1600000
#define NEG_SLOPE 0.2f
#define SCAN_BLK 512
#define FDEG 32          // cached slots per node in fuse

// scratch (device globals — allocation is forbidden)
__device__ __align__(16) __half g_xph[MAXN * HC];    // 12.8 MB (fp16 xp)
__device__ __align__(16) float g_asrc[MAXN * H];
__device__ __align__(16) float g_adst[MAXN * H];
__device__ int  g_cnt[MAXN];        // zero-initialized; self-restored each call
__device__ int  g_rowptr[MAXN];     // partial (within-block) exclusive prefix
__device__ int  g_woff[MAXN];       // copy of partial prefix, atomically bumped
__device__ int  g_bsum[SCAN_BLK];
__device__ int  g_boff[SCAN_BLK];
__device__ int  g_scancnt;          // block-done counter; self-restored
__device__ int2 g_sedge[MAXE];      // (src, orig edge id), dst-sorted

__device__ __forceinline__ unsigned h2_to_u(__half2 h) {
    return *reinterpret_cast<unsigned*>(&h);
}
__device__ __forceinline__ __half2 u_to_h2(unsigned u) {
    return *reinterpret_cast<__half2*>(&u);
}

__device__ __forceinline__ float4 leaky_exp4(float4 as, float4 ad) {
    float4 l;
    l.x = as.x + ad.x; l.x = l.x > 0.f ? l.x : NEG_SLOPE * l.x;
    l.y = as.y + ad.y; l.y = l.y > 0.f ? l.y : NEG_SLOPE * l.y;
    l.z = as.z + ad.z; l.z = l.z > 0.f ? l.z : NEG_SLOPE * l.z;
    l.w = as.w + ad.w; l.w = l.w > 0.f ? l.w : NEG_SLOPE * l.w;
    float4 ev;
    ev.x = __expf(l.x); ev.y = __expf(l.y);
    ev.z = __expf(l.z); ev.w = __expf(l.w);
    return ev;
}

// ---------------------------------------------------------------------------
// K-hist: histogram of dst (int4, 4 atomics/thread). dst half only.
// ---------------------------------------------------------------------------
__global__ void k_hist4(const int* __restrict__ ei, int e) {
    const int4* d4p = (const int4*)(ei + e);
    int q = e >> 2;
    for (int i = blockIdx.x * blockDim.x + threadIdx.x; i < q;
         i += gridDim.x * blockDim.x) {
        int4 d = d4p[i];
        atomicAdd(&g_cnt[d.x], 1);
        atomicAdd(&g_cnt[d.y], 1);
        atomicAdd(&g_cnt[d.z], 1);
        atomicAdd(&g_cnt[d.w], 1);
    }
}
__global__ void k_hist1(const int* __restrict__ ei, int e) {   // fallback
    for (int i = blockIdx.x * blockDim.x + threadIdx.x; i < e;
         i += gridDim.x * blockDim.x)
        atomicAdd(&g_cnt[ei[e + i]], 1);
}

// ---------------------------------------------------------------------------
// K-scan: per-block exclusive scan of g_cnt (self-zeroing) -> rowptr/woff
// (partial); last finished block scans the block sums -> g_boff.
// ---------------------------------------------------------------------------
__global__ __launch_bounds__(SCAN_BLK) void k_scan(int n) {
    __shared__ int s[SCAN_BLK];
    __shared__ int lastdone;
    int t = threadIdx.x;
    int i = blockIdx.x * SCAN_BLK + t;
    int v = 0;
    if (i < n) {
        v = g_cnt[i];
        g_cnt[i] = 0;
    }
    s[t] = v;
    __syncthreads();
    #pragma unroll
    for (int off = 1; off < SCAN_BLK; off <<= 1) {
        int a = (t >= off) ? s[t - off] : 0;
        __syncthreads();
        s[t] += a;
        __syncthreads();
    }
    if (i < n) {
        int r = s[t] - v;
        g_rowptr[i] = r;
        g_woff[i] = r;
    }
    if (t == SCAN_BLK - 1) g_bsum[blockIdx.x] = s[t];

    __threadfence();
    if (t == 0) {
        int d = atomicAdd(&g_scancnt, 1);
        lastdone = (d == gridDim.x - 1);
    }
    __syncthreads();
    if (!lastdone) return;
    int nb = gridDim.x;
    int bv = (t < nb) ? g_bsum[t] : 0;
    s[t] = bv;
    __syncthreads();
    #pragma unroll
    for (int off = 1; off < SCAN_BLK; off <<= 1) {
        int a = (t >= off) ? s[t - off] : 0;
        __syncthreads();
        s[t] += a;
        __syncthreads();
    }
    g_boff[t] = s[t] - bv;
    if (t == 0) g_scancnt = 0;
}

// ---------------------------------------------------------------------------
// K-permute: 4 edges/thread (int4 loads), scatter into dst-sorted order,
// and produce the edge_index float copy.
// ---------------------------------------------------------------------------
__global__ void k_permute4(const int* __restrict__ ei,
                           float* __restrict__ out_ei, int e) {
    int q = e >> 2;
    int i = blockIdx.x * blockDim.x + threadIdx.x;
    if (i >= q) return;
    int4 s4 = ((const int4*)ei)[i];
    int4 d4 = ((const int4*)(ei + e))[i];
    if (out_ei) {
        float4 fs = make_float4((float)s4.x, (float)s4.y,
                                (float)s4.z, (float)s4.w);
        float4 fd = make_float4((float)d4.x, (float)d4.y,
                                (float)d4.z, (float)d4.w);
        ((float4*)out_ei)[i] = fs;
        ((float4*)(out_ei + e))[i] = fd;
    }
    int base = i * 4;
    int r0 = atomicAdd(&g_woff[d4.x], 1) + g_boff[d4.x >> 9];
    int r1 = atomicAdd(&g_woff[d4.y], 1) + g_boff[d4.y >> 9];
    int r2 = atomicAdd(&g_woff[d4.z], 1) + g_boff[d4.z >> 9];
    int r3 = atomicAdd(&g_woff[d4.w], 1) + g_boff[d4.w >> 9];
    g_sedge[r0] = make_int2(s4.x, base);
    g_sedge[r1] = make_int2(s4.y, base + 1);
    g_sedge[r2] = make_int2(s4.z, base + 2);
    g_sedge[r3] = make_int2(s4.w, base + 3);
}
__global__ void k_permute1(const int* __restrict__ ei,
                           float* __restrict__ out_ei, int e) {  // fallback
    int i = blockIdx.x * blockDim.x + threadIdx.x;
    if (i >= e) return;
    int src = ei[i], dst = ei[e + i];
    if (out_ei) { out_ei[i] = (float)src; out_ei[e + i] = (float)dst; }
    int r = atomicAdd(&g_woff[dst], 1) + g_boff[dst >> 9];
    g_sedge[r] = make_int2(src, i);
}

// ---------------------------------------------------------------------------
// K-gemm: xp = x @ W (FFMA, 128 nodes/block, 4x8 tile/thread), fused
// a_src/a_dst in fp32; xp stored as fp16 (halves the fuse gather traffic).
// ---------------------------------------------------------------------------
__global__ __launch_bounds__(256) void k_gemm(
        const float* __restrict__ x, const float* __restrict__ W,
        const float* __restrict__ att_src, const float* __restrict__ att_dst,
        int n) {
    __shared__ float4 sW4[IN_CH * 16];      // 32 KB
    __shared__ float  sx[128 * 129];        // 66 KB
    int tid = threadIdx.x;
    int tx = tid & 7;        // col group: float4 cols 2tx, 2tx+1 (8 cols)
    int ty = tid >> 3;       // node group: nodes 4ty..4ty+3
    int node0 = blockIdx.x * 128;

    const float4* W4 = (const float4*)W;
    #pragma unroll
    for (int i = 0; i < (IN_CH * 16) / 256; i++)
        sW4[tid + i * 256] = W4[tid + i * 256];

    #pragma unroll
    for (int i = 0; i < (128 * IN_CH) / 256; i++) {
        int idx = tid + i * 256;
        int nn = idx >> 7, k = idx & 127;
        int node = node0 + nn;
        sx[nn * 129 + k] = (node < n) ? x[(size_t)node * IN_CH + k] : 0.f;
    }
    __syncthreads();

    float4 acc[4][2];
    #pragma unroll
    for (int j = 0; j < 4; j++) {
        acc[j][0] = make_float4(0.f, 0.f, 0.f, 0.f);
        acc[j][1] = make_float4(0.f, 0.f, 0.f, 0.f);
    }

    #pragma unroll 4
    for (int k = 0; k < IN_CH; k++) {
        float4 w0 = sW4[k * 16 + 2 * tx];
        float4 w1 = sW4[k * 16 + 2 * tx + 1];
        #pragma unroll
        for (int j = 0; j < 4; j++) {
            float xv = sx[(ty * 4 + j) * 129 + k];
            acc[j][0].x = fmaf(xv, w0.x, acc[j][0].x);
            acc[j][0].y = fmaf(xv, w0.y, acc[j][0].y);
            acc[j][0].z = fmaf(xv, w0.z, acc[j][0].z);
            acc[j][0].w = fmaf(xv, w0.w, acc[j][0].w);
            acc[j][1].x = fmaf(xv, w1.x, acc[j][1].x);
            acc[j][1].y = fmaf(xv, w1.y, acc[j][1].y);
            acc[j][1].z = fmaf(xv, w1.z, acc[j][1].z);
            acc[j][1].w = fmaf(xv, w1.w, acc[j][1].w);
        }
    }

    float4 as0 = ((const float4*)att_src)[2 * tx];
    float4 as1 = ((const float4*)att_src)[2 * tx + 1];
    float4 ad0 = ((const float4*)att_dst)[2 * tx];
    float4 ad1 = ((const float4*)att_dst)[2 * tx + 1];
    int head = tx >> 1;

    #pragma unroll
    for (int j = 0; j < 4; j++) {
        int node = node0 + ty * 4 + j;
        if (node < n) {
            // pack 8 cols into 8 halfs = one 16B store
            uint4 packed;
            packed.x = h2_to_u(__floats2half2_rn(acc[j][0].x, acc[j][0].y));
            packed.y = h2_to_u(__floats2half2_rn(acc[j][0].z, acc[j][0].w));
            packed.z = h2_to_u(__floats2half2_rn(acc[j][1].x, acc[j][1].y));
            packed.w = h2_to_u(__floats2half2_rn(acc[j][1].z, acc[j][1].w));
            ((uint4*)&g_xph[(size_t)node * HC])[tx] = packed;
        }
        float s = acc[j][0].x * as0.x + acc[j][0].y * as0.y +
                  acc[j][0].z * as0.z + acc[j][0].w * as0.w +
                  acc[j][1].x * as1.x + acc[j][1].y * as1.y +
                  acc[j][1].z * as1.z + acc[j][1].w * as1.w;
        float d = acc[j][0].x * ad0.x + acc[j][0].y * ad0.y +
                  acc[j][0].z * ad0.z + acc[j][0].w * ad0.w +
                  acc[j][1].x * ad1.x + acc[j][1].y * ad1.y +
                  acc[j][1].z * ad1.z + acc[j][1].w * ad1.w;
        s += __shfl_xor_sync(0xffffffffu, s, 1);
        d += __shfl_xor_sync(0xffffffffu, d, 1);
        if ((tx & 1) == 0 && node < n) {
            g_asrc[node * H + head] = s;
            g_adst[node * H + head] = d;
        }
    }
}

// ---------------------------------------------------------------------------
// K-fuse: HALF-WARP (16 lanes) per dst node. Lane owns 4 cols.
// xp gathered as fp16 (8B/lane), accumulated fp32.
// ---------------------------------------------------------------------------
__global__ __launch_bounds__(256) void k_fuse(
        const float* __restrict__ bias, float* __restrict__ out,
        float* __restrict__ out_alpha, int n, int e) {
    __shared__ float4 s_ev[16][FDEG];   // 8 KB
    __shared__ int2   s_se[16][FDEG];   // 4 KB
    int g = threadIdx.x >> 4;
    int l = threadIdx.x & 15;
    unsigned gmask = 0xFFFFu << ((g & 1) * 16);
    int node = blockIdx.x * 16 + g;
    if (node >= n) return;
    int start = g_rowptr[node] + g_boff[node >> 9];
    int end = (node == n - 1) ? e
            : g_rowptr[node + 1] + g_boff[(node + 1) >> 9];
    int deg = end - start;
    float4 ad = ((const float4*)g_adst)[node];

    // pass 1: ev cache + denominator
    float4 sum = make_float4(0.f, 0.f, 0.f, 0.f);
    for (int slot = l; slot < deg; slot += 16) {
        int2 se = g_sedge[start + slot];
        float4 as = ((const float4*)g_asrc)[se.x];
        float4 ev = leaky_exp4(as, ad);
        if (slot < FDEG) {
            s_ev[g][slot] = ev;
            s_se[g][slot] = se;
        }
        sum.x += ev.x; sum.y += ev.y; sum.z += ev.z; sum.w += ev.w;
    }
    #pragma unroll
    for (int off = 8; off >= 1; off >>= 1) {
        sum.x += __shfl_xor_sync(gmask, sum.x, off);
        sum.y += __shfl_xor_sync(gmask, sum.y, off);
        sum.z += __shfl_xor_sync(gmask, sum.z, off);
        sum.w += __shfl_xor_sync(gmask, sum.w, off);
    }
    float4 inv;
    inv.x = 1.f / (sum.x + 1e-16f);
    inv.y = 1.f / (sum.y + 1e-16f);
    inv.z = 1.f / (sum.z + 1e-16f);
    inv.w = 1.f / (sum.w + 1e-16f);
    __syncwarp(gmask);

    int h = l >> 2;
    float invh = (h == 0) ? inv.x : (h == 1) ? inv.y :
                 (h == 2) ? inv.z : inv.w;
    float4 acc = make_float4(0.f, 0.f, 0.f, 0.f);

    for (int base = 0; base < deg; base += 16) {
        int m = deg - base; if (m > 16) m = 16;
        int slot = base + l;
        if (slot >= FDEG && l < m) {
            int2 se = g_sedge[start + slot];
            float4 as = ((const float4*)g_asrc)[se.x];
            s_ev[g][slot & (FDEG - 1)] = leaky_exp4(as, ad);
            s_se[g][slot & (FDEG - 1)] = se;
        }
        __syncwarp(gmask);
        if (l < m && out_alpha) {
            int idx = slot & (FDEG - 1);
            float4 ev = s_ev[g][idx];
            float4 al;
            al.x = ev.x * inv.x; al.y = ev.y * inv.y;
            al.z = ev.z * inv.z; al.w = ev.w * inv.w;
            ((float4*)out_alpha)[s_se[g][idx].y] = al;
        }
        #pragma unroll 4
        for (int j = 0; j < m; j++) {
            int idx = (base + j) & (FDEG - 1);
            int src = s_se[g][idx].x;                      // LDS broadcast
            float a = ((const float*)&s_ev[g][idx])[h] * invh;
            uint2 raw = ((const uint2*)&g_xph[(size_t)src * HC])[l];
            float2 f0 = __half22float2(u_to_h2(raw.x));
            float2 f1 = __half22float2(u_to_h2(raw.y));
            acc.x = fmaf(f0.x, a, acc.x);
            acc.y = fmaf(f0.y, a, acc.y);
            acc.z = fmaf(f1.x, a, acc.z);
            acc.w = fmaf(f1.y, a, acc.w);
        }
        __syncwarp(gmask);
    }
    float4 b = ((const float4*)bias)[l];
    float4 o;
    o.x = acc.x + b.x; o.y = acc.y + b.y;
    o.z = acc.z + b.z; o.w = acc.w + b.w;
    ((float4*)&out[(size_t)node * HC])[l] = o;
}

// lazily-created side stream + events (resource init only; the launched work
// is identical on every call, so graph capture sees the same graph each time)
static cudaStream_t g_s2 = nullptr;
static cudaEvent_t  g_evFork = nullptr, g_evJoin = nullptr;

extern "C" void kernel_launch(void* const* d_in, const int* in_sizes, int n_in,
                              void* d_out, int out_size) {
    const float* x       = (const float*)d_in[0];
    const float* W       = (const float*)d_in[1];
    const float* att_src = (const float*)d_in[2];
    const float* att_dst = (const float*)d_in[3];
    const float* bias    = (const float*)d_in[4];
    const int*   ei      = (const int*)d_in[5];

    if (!g_s2) {
        cudaStreamCreateWithFlags(&g_s2, cudaStreamNonBlocking);
        cudaEventCreateWithFlags(&g_evFork, cudaEventDisableTiming);
        cudaEventCreateWithFlags(&g_evJoin, cudaEventDisableTiming);
    }

    int n = in_sizes[0] / IN_CH;
    int e = in_sizes[5] / 2;

    float* out = (float*)d_out;
    float* out_ei = nullptr;
    float* out_alpha = nullptr;
    if (out_size >= n * HC + 2 * e) out_ei = out + (size_t)n * HC;
    if (out_size >= n * HC + 2 * e + e * H)
        out_alpha = out + (size_t)n * HC + 2 * e;

    // ---- fork: GEMM on side stream (independent of CSR build) ----
    cudaEventRecord(g_evFork, 0);
    cudaStreamWaitEvent(g_s2, g_evFork, 0);
    k_gemm<<<(n + 127) / 128, 256, 0, g_s2>>>(x, W, att_src, att_dst, n);
    cudaEventRecord(g_evJoin, g_s2);

    // ---- main stream: CSR build ----
    bool vec = ((e & 3) == 0);
    if (vec) {
        int q = e >> 2;
        int blocks = (q + 255) / 256;
        if (blocks > 2048) blocks = 2048;
        k_hist4<<<blocks, 256>>>(ei, e);
    } else {
        int blocks = (e + 255) / 256;
        if (blocks > 4096) blocks = 4096;
        k_hist1<<<blocks, 256>>>(ei, e);
    }
    int nb = (n + SCAN_BLK - 1) / SCAN_BLK;
    k_scan<<<nb, SCAN_BLK>>>(n);
    if (vec) {
        int q = e >> 2;
        k_permute4<<<(q + 255) / 256, 256>>>(ei, out_ei, e);
    } else {
        k_permute1<<<(e + 255) / 256, 256>>>(ei, out_ei, e);
    }

    // ---- join: fuse needs both GEMM results and sorted edges ----
    cudaStreamWaitEvent(0, g_evJoin, 0);
    k_fuse<<<(n + 15) / 16, 256>>>(bias, out, out_alpha, n, e);
}